// round 3
// baseline (speedup 1.0000x reference)
#include <cuda_runtime.h>

#define BB 4
#define CC 64
#define NN 8192
#define OO 128
#define KK 20
#define SEG 2
#define SEGN (NN / SEG)

typedef unsigned long long u64;

// Scratch (static device allocations — no cudaMalloc anywhere)
__device__ __align__(16) float g_xt[(size_t)BB * NN * CC];  // x^T: [b][n][c]
__device__ float g_xx[BB * NN];                 // 0.5 * squared norms
__device__ int   g_knn[(size_t)BB * NN * KK];   // final top-K indices
__device__ float g_segv[(size_t)BB * NN * SEG * KK];  // per-segment top-K vals
__device__ int   g_segi[(size_t)BB * NN * SEG * KK];  // per-segment top-K idxs
__device__ float g_W1at[CC * CC];               // [j][c] = W1[c][j],    c<64
__device__ float g_W1bt[CC * CC];               // [j][c] = W1[c][64+j], c<64
__device__ float g_W2pf[2 * CC * OO];           // pair-interleaved: [c/2][o][2]

// ---- packed fp32x2 helpers (bit-exact fp32, 2 MACs/issue) -----------------
__device__ __forceinline__ u64 fma2(u64 a, u64 b, u64 c) {
    u64 d; asm("fma.rn.f32x2 %0, %1, %2, %3;" : "=l"(d) : "l"(a), "l"(b), "l"(c));
    return d;
}
__device__ __forceinline__ u64 add2(u64 a, u64 b) {
    u64 d; asm("add.rn.f32x2 %0, %1, %2;" : "=l"(d) : "l"(a), "l"(b));
    return d;
}
__device__ __forceinline__ u64 pack2(float lo, float hi) {
    u64 d; asm("mov.b64 %0, {%1, %2};" : "=l"(d) : "f"(lo), "f"(hi));
    return d;
}
__device__ __forceinline__ void unpack2(float& lo, float& hi, u64 v) {
    asm("mov.b64 {%0, %1}, %2;" : "=f"(lo), "=f"(hi) : "l"(v));
}

// ---------------------------------------------------------------------------
// Prep: tiled transpose x -> xt[b][n][c] (coalesced both sides) + 0.5*norms
// ---------------------------------------------------------------------------
__global__ __launch_bounds__(256) void prep_x_kernel(const float* __restrict__ x) {
    int b = blockIdx.y;
    int n0 = blockIdx.x * 32;
    __shared__ float sh[CC][33];
    const float* xb = x + (size_t)b * CC * NN;
    int tid = threadIdx.x;
#pragma unroll
    for (int it = 0; it < 8; it++) {
        int e = it * 256 + tid;
        int c = e >> 5, nl = e & 31;
        sh[c][nl] = __ldg(&xb[(size_t)c * NN + n0 + nl]);  // coalesced
    }
    __syncthreads();
#pragma unroll
    for (int it = 0; it < 8; it++) {
        int e = it * 256 + tid;
        int nl = e >> 6, c = e & 63;
        g_xt[((size_t)b * NN + n0 + nl) * CC + c] = sh[c][nl];  // coalesced
    }
    if (tid < 32) {
        float s = 0.f;
#pragma unroll
        for (int c = 0; c < CC; c++) { float v = sh[c][tid]; s += v * v; }
        g_xx[b * NN + n0 + tid] = 0.5f * s;
    }
}

// ---------------------------------------------------------------------------
// Prep weights. Only W1 rows c<64 needed (softmax over k sums to 1, so gate
// columns c>=64 contribute exactly center). W2 stored pair-interleaved.
// ---------------------------------------------------------------------------
__global__ void prep_w_kernel(const float* __restrict__ W1,
                              const float* __restrict__ W2) {
    int t = blockIdx.x * 256 + threadIdx.x;  // 0..32767
    if (t < 128 * 128) {
        int c = t >> 7, j = t & 127;
        float v = W1[t];
        if (c < CC) {
            if (j < CC) g_W1at[j * CC + c] = v;
            else        g_W1bt[(j - CC) * CC + c] = v;
        }
    } else {
        int t2 = t - 128 * 128;
        int o = t2 >> 7, c = t2 & 127;
        g_W2pf[((c >> 1) * OO + o) * 2 + (c & 1)] = W2[t2];
    }
}

// ---------------------------------------------------------------------------
// Top-K insertion (sorted desc, static indices). Strict '>' keeps earliest
// index on ties, matching jax.lax.top_k.
// ---------------------------------------------------------------------------
__device__ __forceinline__ void topk_insert(float (&vals)[KK], int (&idxs)[KK],
                                            float v, int j) {
    vals[KK - 1] = v;
    idxs[KK - 1] = j;
#pragma unroll
    for (int p = KK - 1; p > 0; --p) {
        if (vals[p] > vals[p - 1]) {
            float tv = vals[p]; vals[p] = vals[p - 1]; vals[p - 1] = tv;
            int   ti = idxs[p]; idxs[p] = idxs[p - 1]; idxs[p - 1] = ti;
        }
    }
}

// ---------------------------------------------------------------------------
// KNN (segmented): each block handles 128 queries x one half of the
// candidates; rank = dot - 0.5*||xj||^2 (monotone in pd; xxi constant/query).
// Inner loop per j per warp: 16 LDS.128 broadcast + 32 FFMA2 + ~6 epilogue.
// ---------------------------------------------------------------------------
__global__ __launch_bounds__(128) void knn_kernel() {
    int b = blockIdx.y;
    int seg = blockIdx.x & (SEG - 1);
    int i = (blockIdx.x >> 1) * 128 + threadIdx.x;
    __shared__ __align__(16) float shx[128][CC];
    __shared__ float shxx[128];
    const float* xtb = g_xt + (size_t)b * NN * CC;

    u64 xi2[32];
    const float4* xir = (const float4*)(xtb + (size_t)i * CC);
#pragma unroll
    for (int q = 0; q < 16; q++) {
        float4 t = __ldg(&xir[q]);
        xi2[2 * q + 0] = pack2(t.x, t.y);
        xi2[2 * q + 1] = pack2(t.z, t.w);
    }

    float vals[KK]; int idxs[KK];
#pragma unroll
    for (int k = 0; k < KK; k++) { vals[k] = -3.0e38f; idxs[k] = 0; }

    int jend = (seg + 1) * SEGN;
    for (int j0 = seg * SEGN; j0 < jend; j0 += 128) {
        __syncthreads();
        const float4* src = (const float4*)(xtb + (size_t)j0 * CC);
        float4* dst = (float4*)shx;
#pragma unroll
        for (int r = 0; r < 16; r++) {
            int lin = r * 128 + threadIdx.x;
            dst[lin] = __ldg(&src[lin]);
        }
        shxx[threadIdx.x] = g_xx[b * NN + j0 + threadIdx.x];
        __syncthreads();

#pragma unroll 4
        for (int jl = 0; jl < 128; jl++) {
            const ulonglong2* row = (const ulonglong2*)shx[jl];  // broadcast
            u64 a0 = 0ull, a1 = 0ull, a2 = 0ull, a3 = 0ull;
#pragma unroll
            for (int q = 0; q < 8; q++) {
                ulonglong2 v0 = row[2 * q];
                ulonglong2 v1 = row[2 * q + 1];
                a0 = fma2(xi2[4 * q + 0], v0.x, a0);
                a1 = fma2(xi2[4 * q + 1], v0.y, a1);
                a2 = fma2(xi2[4 * q + 2], v1.x, a2);
                a3 = fma2(xi2[4 * q + 3], v1.y, a3);
            }
            a0 = add2(a0, a1);
            a2 = add2(a2, a3);
            a0 = add2(a0, a2);
            float lo, hi; unpack2(lo, hi, a0);
            float rank = lo + hi - shxx[jl];
            if (rank > vals[KK - 1]) topk_insert(vals, idxs, rank, j0 + jl);
        }
    }
    size_t ob = ((size_t)(b * NN + i) * SEG + seg) * KK;
#pragma unroll
    for (int k = 0; k < KK; k++) { g_segv[ob + k] = vals[k]; g_segi[ob + k] = idxs[k]; }
}

// ---------------------------------------------------------------------------
// Merge two sorted top-K lists into global top-K. Strict '>' prefers segment
// 0 (lower indices) on ties -> matches jax tie-breaking.
// ---------------------------------------------------------------------------
__global__ void merge_kernel() {
    int t = blockIdx.x * 256 + threadIdx.x;  // b*NN + i
    size_t base = (size_t)t * SEG * KK;
    const float* v = g_segv + base;
    const int* id = g_segi + base;
    float h0 = v[0], h1 = v[KK];
    int p0 = 0, p1 = 0;
    int* out = g_knn + (size_t)t * KK;
#pragma unroll
    for (int k = 0; k < KK; k++) {
        if (h1 > h0) {
            out[k] = id[KK + p1];
            p1++;
            h1 = (p1 < KK) ? v[KK + p1] : -3.0e38f;
        } else {
            out[k] = id[p0];
            p0++;
            h0 = (p0 < KK) ? v[p0] : -3.0e38f;
        }
    }
}

// ---------------------------------------------------------------------------
// Fused MLP: 4 points/block; thread (p = tid>>6, c = tid&63) owns column c
// (<64) of point p. h[k][c] via FFMA2; softmax over k; g; out = W2 @ g.
// ---------------------------------------------------------------------------
__global__ __launch_bounds__(256) void mlp_kernel(float* __restrict__ out) {
    int b = blockIdx.y;
    int n0 = blockIdx.x * 4;
    int tid = threadIdx.x;
    int p = tid >> 6, c = tid & 63;

    __shared__ __align__(16) float nbrT[4][CC][24];  // diff[j][k], pitch 24
    __shared__ float xi_sh[4][CC];
    __shared__ int   idx_sh[4][KK];
    __shared__ __align__(16) float g_sh[4][2 * CC];

    const float* xtb = g_xt + (size_t)b * NN * CC;

    if (tid < 4 * KK) {
        int pp = tid / KK, k = tid % KK;
        idx_sh[pp][k] = g_knn[((size_t)b * NN + n0 + pp) * KK + k];
    }
    xi_sh[p][c] = __ldg(&xtb[(size_t)(n0 + p) * CC + c]);
    __syncthreads();

    // gather neighbors, diff = xj - xi, stored transposed [c][k]
    for (int pp = 0; pp < 4; pp++) {
        for (int e = tid; e < KK * CC; e += 256) {
            int k = e >> 6, cc = e & 63;
            nbrT[pp][cc][k] =
                __ldg(&xtb[(size_t)idx_sh[pp][k] * CC + cc]) - xi_sh[pp][cc];
        }
    }
    __syncthreads();

    // h[k] for this thread's column c (<64) of point p, packed f32x2
    u64 h2[KK / 2];
#pragma unroll
    for (int q = 0; q < KK / 2; q++) h2[q] = 0ull;
    float base = 0.f;
#pragma unroll 8
    for (int j = 0; j < CC; j++) {
        float w = __ldg(&g_W1at[j * CC + c]);
        u64 w2 = pack2(w, w);
        base += __ldg(&g_W1bt[j * CC + c]) * xi_sh[p][j];
        const ulonglong2* f2 = (const ulonglong2*)nbrT[p][j];  // broadcast
#pragma unroll
        for (int q = 0; q < 5; q++) {
            ulonglong2 f = f2[q];
            h2[2 * q + 0] = fma2(w2, f.x, h2[2 * q + 0]);
            h2[2 * q + 1] = fma2(w2, f.y, h2[2 * q + 1]);
        }
    }

    float h[KK];
#pragma unroll
    for (int q = 0; q < KK / 2; q++) unpack2(h[2 * q], h[2 * q + 1], h2[q]);

    // softmax over k, then g
    float m = -3.0e38f;
#pragma unroll
    for (int k = 0; k < KK; k++) { h[k] += base; m = fmaxf(m, h[k]); }
    float s = 0.f;
#pragma unroll
    for (int k = 0; k < KK; k++) { h[k] = __expf(h[k] - m); s += h[k]; }
    float inv = 1.f / s;
    float gdiff = 0.f;
#pragma unroll
    for (int k = 0; k < KK; k++) gdiff += nbrT[p][c][k] * h[k];
    g_sh[p][c]      = gdiff * inv;
    g_sh[p][CC + c] = xi_sh[p][c];  // softmax sums to 1 -> center passthrough
    __syncthreads();

    // out[o] = sum_c W2[o][c]*g[c] via FFMA2 (W2 pair-interleaved)
    int o = tid & 127;
    int pb = (tid >> 7) * 2;
    const u64* w2p = (const u64*)g_W2pf;
    for (int r = 0; r < 2; r++) {
        int pp = pb + r;
        const u64* gp = (const u64*)g_sh[pp];
        u64 acc2 = 0ull;
#pragma unroll 16
        for (int c2 = 0; c2 < CC; c2++)
            acc2 = fma2(__ldg(&w2p[c2 * OO + o]), gp[c2], acc2);
        float lo, hi; unpack2(lo, hi, acc2);
        out[(size_t)b * OO * NN + (size_t)o * NN + (n0 + pp)] = lo + hi;
    }
}

// ---------------------------------------------------------------------------
extern "C" void kernel_launch(void* const* d_in, const int* in_sizes, int n_in,
                              void* d_out, int out_size) {
    const float* x  = (const float*)d_in[0];
    const float* W1 = (const float*)d_in[1];
    const float* W2 = (const float*)d_in[2];
    float* out = (float*)d_out;

    prep_x_kernel<<<dim3(NN / 32, BB), 256>>>(x);
    prep_w_kernel<<<128, 256>>>(W1, W2);
    knn_kernel<<<dim3((NN / 128) * SEG, BB), 128>>>();
    merge_kernel<<<BB * NN / 256, 256>>>();
    mlp_kernel<<<dim3(NN / 4, BB), 256>>>(out);
}

// round 4
// speedup vs baseline: 1.1315x; 1.1315x over previous
#include <cuda_runtime.h>

#define BB 4
#define CC 64
#define NN 8192
#define OO 128
#define KK 20
#define SEG 4
#define SEGN (NN / SEG)

typedef unsigned long long u64;

// Scratch (static device allocations — no cudaMalloc anywhere)
__device__ __align__(16) float g_xt[(size_t)BB * NN * CC];  // x^T: [b][n][c]
__device__ float g_xx[BB * NN];                 // 0.5 * squared norms
__device__ int   g_knn[(size_t)BB * NN * KK];   // final top-K indices
__device__ float g_segv[(size_t)BB * NN * SEG * KK];  // per-segment top-K vals
__device__ int   g_segi[(size_t)BB * NN * SEG * KK];  // per-segment top-K idxs
__device__ float g_W1at[CC * CC];               // [j][c] = W1[c][j],    c<64
__device__ float g_W1bt[CC * CC];               // [j][c] = W1[c][64+j], c<64
__device__ float g_W2t[2 * CC * OO];            // [c][o] = W2[o][c]

// ---- packed fp32x2 helpers (bit-exact fp32, 2 MACs/issue) -----------------
__device__ __forceinline__ u64 fma2(u64 a, u64 b, u64 c) {
    u64 d; asm("fma.rn.f32x2 %0, %1, %2, %3;" : "=l"(d) : "l"(a), "l"(b), "l"(c));
    return d;
}
__device__ __forceinline__ u64 add2(u64 a, u64 b) {
    u64 d; asm("add.rn.f32x2 %0, %1, %2;" : "=l"(d) : "l"(a), "l"(b));
    return d;
}
__device__ __forceinline__ u64 pack2(float lo, float hi) {
    u64 d; asm("mov.b64 %0, {%1, %2};" : "=l"(d) : "f"(lo), "f"(hi));
    return d;
}
__device__ __forceinline__ void unpack2(float& lo, float& hi, u64 v) {
    asm("mov.b64 {%0, %1}, %2;" : "=f"(lo), "=f"(hi) : "l"(v));
}

// ---------------------------------------------------------------------------
// Prep: tiled transpose x -> xt[b][n][c] (coalesced both sides) + 0.5*norms
// ---------------------------------------------------------------------------
__global__ __launch_bounds__(256) void prep_x_kernel(const float* __restrict__ x) {
    int b = blockIdx.y;
    int n0 = blockIdx.x * 32;
    __shared__ float sh[CC][33];
    const float* xb = x + (size_t)b * CC * NN;
    int tid = threadIdx.x;
#pragma unroll
    for (int it = 0; it < 8; it++) {
        int e = it * 256 + tid;
        int c = e >> 5, nl = e & 31;
        sh[c][nl] = __ldg(&xb[(size_t)c * NN + n0 + nl]);  // coalesced
    }
    __syncthreads();
#pragma unroll
    for (int it = 0; it < 8; it++) {
        int e = it * 256 + tid;
        int nl = e >> 6, c = e & 63;
        g_xt[((size_t)b * NN + n0 + nl) * CC + c] = sh[c][nl];  // coalesced
    }
    if (tid < 32) {
        float s = 0.f;
#pragma unroll
        for (int c = 0; c < CC; c++) { float v = sh[c][tid]; s += v * v; }
        g_xx[b * NN + n0 + tid] = 0.5f * s;
    }
}

// ---------------------------------------------------------------------------
// Prep weights (round-2 layout). Only W1 rows c<64 needed (softmax over k
// sums to 1, so gate columns c>=64 contribute exactly center).
// ---------------------------------------------------------------------------
__global__ void prep_w_kernel(const float* __restrict__ W1,
                              const float* __restrict__ W2) {
    int t = blockIdx.x * 256 + threadIdx.x;  // 0..32767
    if (t < 128 * 128) {
        int c = t >> 7, j = t & 127;
        float v = W1[t];
        if (c < CC) {
            if (j < CC) g_W1at[j * CC + c] = v;
            else        g_W1bt[(j - CC) * CC + c] = v;
        }
    } else {
        int t2 = t - 128 * 128;
        int o = t2 >> 7, c2 = t2 & 127;
        g_W2t[c2 * OO + o] = W2[t2];
    }
}

// ---------------------------------------------------------------------------
// Top-K insertion (sorted desc, static indices). Strict '>' keeps earliest
// index on ties, matching jax.lax.top_k.
// ---------------------------------------------------------------------------
__device__ __forceinline__ void topk_insert(float (&vals)[KK], int (&idxs)[KK],
                                            float v, int j) {
    vals[KK - 1] = v;
    idxs[KK - 1] = j;
#pragma unroll
    for (int p = KK - 1; p > 0; --p) {
        if (vals[p] > vals[p - 1]) {
            float tv = vals[p]; vals[p] = vals[p - 1]; vals[p - 1] = tv;
            int   ti = idxs[p]; idxs[p] = idxs[p - 1]; idxs[p - 1] = ti;
        }
    }
}

// ---------------------------------------------------------------------------
// KNN (segmented, SEG=4): block = 128 queries x one quarter of candidates.
// rank = dot - 0.5*||xj||^2 (monotone in pd; xxi constant per query).
// Inner loop per j per warp: 16 LDS.128 broadcast + 32 FFMA2 + ~6 epilogue.
// ---------------------------------------------------------------------------
__global__ __launch_bounds__(128) void knn_kernel() {
    int b = blockIdx.y;
    int seg = blockIdx.x & (SEG - 1);
    int i = (blockIdx.x >> 2) * 128 + threadIdx.x;
    __shared__ __align__(16) float shx[128][CC];
    __shared__ float shxx[128];
    const float* xtb = g_xt + (size_t)b * NN * CC;

    u64 xi2[32];
    const float4* xir = (const float4*)(xtb + (size_t)i * CC);
#pragma unroll
    for (int q = 0; q < 16; q++) {
        float4 t = __ldg(&xir[q]);
        xi2[2 * q + 0] = pack2(t.x, t.y);
        xi2[2 * q + 1] = pack2(t.z, t.w);
    }

    float vals[KK]; int idxs[KK];
#pragma unroll
    for (int k = 0; k < KK; k++) { vals[k] = -3.0e38f; idxs[k] = 0; }

    int jend = (seg + 1) * SEGN;
    for (int j0 = seg * SEGN; j0 < jend; j0 += 128) {
        __syncthreads();
        const float4* src = (const float4*)(xtb + (size_t)j0 * CC);
        float4* dst = (float4*)shx;
#pragma unroll
        for (int r = 0; r < 16; r++) {
            int lin = r * 128 + threadIdx.x;
            dst[lin] = __ldg(&src[lin]);
        }
        shxx[threadIdx.x] = g_xx[b * NN + j0 + threadIdx.x];
        __syncthreads();

#pragma unroll 4
        for (int jl = 0; jl < 128; jl++) {
            const ulonglong2* row = (const ulonglong2*)shx[jl];  // broadcast
            u64 a0 = 0ull, a1 = 0ull, a2 = 0ull, a3 = 0ull;
#pragma unroll
            for (int q = 0; q < 8; q++) {
                ulonglong2 v0 = row[2 * q];
                ulonglong2 v1 = row[2 * q + 1];
                a0 = fma2(xi2[4 * q + 0], v0.x, a0);
                a1 = fma2(xi2[4 * q + 1], v0.y, a1);
                a2 = fma2(xi2[4 * q + 2], v1.x, a2);
                a3 = fma2(xi2[4 * q + 3], v1.y, a3);
            }
            a0 = add2(a0, a1);
            a2 = add2(a2, a3);
            a0 = add2(a0, a2);
            float lo, hi; unpack2(lo, hi, a0);
            float rank = lo + hi - shxx[jl];
            if (rank > vals[KK - 1]) topk_insert(vals, idxs, rank, j0 + jl);
        }
    }
    size_t ob = ((size_t)(b * NN + i) * SEG + seg) * KK;
#pragma unroll
    for (int k = 0; k < KK; k++) { g_segv[ob + k] = vals[k]; g_segi[ob + k] = idxs[k]; }
}

// ---------------------------------------------------------------------------
// Merge SEG sorted top-K lists into global top-K. Strict '>' prefers the
// earliest segment (lower candidate indices) on ties -> jax tie-breaking.
// ---------------------------------------------------------------------------
__global__ void merge_kernel() {
    int t = blockIdx.x * 256 + threadIdx.x;  // b*NN + i
    size_t base = (size_t)t * SEG * KK;
    const float* v = g_segv + base;
    const int* id = g_segi + base;
    float hd[SEG]; int pos[SEG];
#pragma unroll
    for (int s = 0; s < SEG; s++) { hd[s] = v[s * KK]; pos[s] = 0; }
    int* out = g_knn + (size_t)t * KK;
#pragma unroll
    for (int k = 0; k < KK; k++) {
        int best = 0;
        float bv = hd[0];
#pragma unroll
        for (int s = 1; s < SEG; s++) {
            if (hd[s] > bv) { bv = hd[s]; best = s; }
        }
#pragma unroll
        for (int s = 0; s < SEG; s++) {
            if (s == best) {
                out[k] = id[s * KK + pos[s]];
                pos[s]++;
                hd[s] = (pos[s] < KK) ? v[s * KK + pos[s]] : -3.0e38f;
            }
        }
    }
}

// ---------------------------------------------------------------------------
// Fused MLP (exact round-2 code, known 358us): 4 points/block; thread
// (p = tid>>6, c = tid&63) owns column c (<64) of point p.
// ---------------------------------------------------------------------------
__global__ __launch_bounds__(256) void mlp_kernel(float* __restrict__ out) {
    int b = blockIdx.y;
    int n0 = blockIdx.x * 4;
    int tid = threadIdx.x;
    int p = tid >> 6, c = tid & 63;

    __shared__ __align__(16) float nbrT[4][CC][24];  // diff[j][k], pitch 24
    __shared__ float xi_sh[4][CC];
    __shared__ int   idx_sh[4][KK];
    __shared__ float g_sh[4][2 * CC];

    const float* xtb = g_xt + (size_t)b * NN * CC;

    if (tid < 4 * KK) {
        int pp = tid / KK, k = tid % KK;
        idx_sh[pp][k] = g_knn[((size_t)b * NN + n0 + pp) * KK + k];
    }
    xi_sh[p][c] = __ldg(&xtb[(size_t)(n0 + p) * CC + c]);
    __syncthreads();

    // gather neighbors and form diff = xj - xi, stored transposed [c][k]
    for (int pp = 0; pp < 4; pp++) {
        for (int e = tid; e < KK * CC; e += 256) {
            int k = e >> 6, cc = e & 63;
            nbrT[pp][cc][k] =
                __ldg(&xtb[(size_t)idx_sh[pp][k] * CC + cc]) - xi_sh[pp][cc];
        }
    }
    __syncthreads();

    // h[k] for this thread's column c (<64) of point p
    float h[KK];
#pragma unroll
    for (int k = 0; k < KK; k++) h[k] = 0.f;
    float base = 0.f;
#pragma unroll 8
    for (int j = 0; j < CC; j++) {
        float w  = __ldg(&g_W1at[j * CC + c]);          // coalesced, L1-hot
        base    += __ldg(&g_W1bt[j * CC + c]) * xi_sh[p][j];
        const float4* f4 = (const float4*)nbrT[p][j];   // broadcast
#pragma unroll
        for (int q = 0; q < 5; q++) {
            float4 f = f4[q];
            h[4 * q + 0] += f.x * w;
            h[4 * q + 1] += f.y * w;
            h[4 * q + 2] += f.z * w;
            h[4 * q + 3] += f.w * w;
        }
    }

    // softmax over k, then g
    float m = -3.0e38f;
#pragma unroll
    for (int k = 0; k < KK; k++) { h[k] += base; m = fmaxf(m, h[k]); }
    float s = 0.f;
#pragma unroll
    for (int k = 0; k < KK; k++) { h[k] = __expf(h[k] - m); s += h[k]; }
    float inv = 1.f / s;
    float gdiff = 0.f;
#pragma unroll
    for (int k = 0; k < KK; k++) gdiff += nbrT[p][c][k] * h[k];
    g_sh[p][c]      = gdiff * inv;
    g_sh[p][CC + c] = xi_sh[p][c];  // softmax sums to 1 -> center passthrough
    __syncthreads();

    // out[o] = sum_c W2[o][c] * g[c]
    int o = tid & 127;
    int pb = (tid >> 7) * 2;
    for (int r = 0; r < 2; r++) {
        int pp = pb + r;
        float acc = 0.f;
#pragma unroll 16
        for (int cc = 0; cc < 2 * CC; cc++)
            acc += __ldg(&g_W2t[cc * OO + o]) * g_sh[pp][cc];
        out[(size_t)b * OO * NN + (size_t)o * NN + (n0 + pp)] = acc;
    }
}

// ---------------------------------------------------------------------------
extern "C" void kernel_launch(void* const* d_in, const int* in_sizes, int n_in,
                              void* d_out, int out_size) {
    const float* x  = (const float*)d_in[0];
    const float* W1 = (const float*)d_in[1];
    const float* W2 = (const float*)d_in[2];
    float* out = (float*)d_out;

    prep_x_kernel<<<dim3(NN / 32, BB), 256>>>(x);
    prep_w_kernel<<<128, 256>>>(W1, W2);
    knn_kernel<<<dim3((NN / 128) * SEG, BB), 128>>>();
    merge_kernel<<<BB * NN / 256, 256>>>();
    mlp_kernel<<<dim3(NN / 4, BB), 256>>>(out);
}

// round 5
// speedup vs baseline: 1.3123x; 1.1598x over previous
#include <cuda_runtime.h>

#define BB 4
#define CC 64
#define NN 8192
#define OO 128
#define KK 20

typedef unsigned long long u64;

// Scratch (static device allocations — no cudaMalloc anywhere)
__device__ __align__(16) float g_xt[(size_t)BB * NN * CC];  // x^T: [b][n][c]
__device__ float g_xx[BB * NN];                 // 0.5 * squared norms
__device__ int   g_knn[(size_t)BB * NN * KK];   // top-K indices
__device__ float g_W1at[CC * CC];               // [j][c] = W1[c][j],    c<64
__device__ float g_W1bt[CC * CC];               // [j][c] = W1[c][64+j], c<64
__device__ float g_W2t[2 * CC * OO];            // [c][o] = W2[o][c]

// ---- packed fp32x2 helpers (bit-exact fp32, 2 MACs/issue) -----------------
__device__ __forceinline__ u64 fma2(u64 a, u64 b, u64 c) {
    u64 d; asm("fma.rn.f32x2 %0, %1, %2, %3;" : "=l"(d) : "l"(a), "l"(b), "l"(c));
    return d;
}
__device__ __forceinline__ u64 add2(u64 a, u64 b) {
    u64 d; asm("add.rn.f32x2 %0, %1, %2;" : "=l"(d) : "l"(a), "l"(b));
    return d;
}
__device__ __forceinline__ u64 pack2(float lo, float hi) {
    u64 d; asm("mov.b64 %0, {%1, %2};" : "=l"(d) : "f"(lo), "f"(hi));
    return d;
}
__device__ __forceinline__ void unpack2(float& lo, float& hi, u64 v) {
    asm("mov.b64 {%0, %1}, %2;" : "=f"(lo), "=f"(hi) : "l"(v));
}

// ---------------------------------------------------------------------------
// Prep: tiled transpose x -> xt[b][n][c] (coalesced both sides) + 0.5*norms
// ---------------------------------------------------------------------------
__global__ __launch_bounds__(256) void prep_x_kernel(const float* __restrict__ x) {
    int b = blockIdx.y;
    int n0 = blockIdx.x * 32;
    __shared__ float sh[CC][33];
    const float* xb = x + (size_t)b * CC * NN;
    int tid = threadIdx.x;
#pragma unroll
    for (int it = 0; it < 8; it++) {
        int e = it * 256 + tid;
        int c = e >> 5, nl = e & 31;
        sh[c][nl] = __ldg(&xb[(size_t)c * NN + n0 + nl]);  // coalesced
    }
    __syncthreads();
#pragma unroll
    for (int it = 0; it < 8; it++) {
        int e = it * 256 + tid;
        int nl = e >> 6, c = e & 63;
        g_xt[((size_t)b * NN + n0 + nl) * CC + c] = sh[c][nl];  // coalesced
    }
    if (tid < 32) {
        float s = 0.f;
#pragma unroll
        for (int c = 0; c < CC; c++) { float v = sh[c][tid]; s += v * v; }
        g_xx[b * NN + n0 + tid] = 0.5f * s;
    }
}

// ---------------------------------------------------------------------------
// Prep weights. Only W1 rows c<64 needed (softmax over k sums to 1, so gate
// columns c>=64 contribute exactly center).
// ---------------------------------------------------------------------------
__global__ void prep_w_kernel(const float* __restrict__ W1,
                              const float* __restrict__ W2) {
    int t = blockIdx.x * 256 + threadIdx.x;  // 0..32767
    if (t < 128 * 128) {
        int c = t >> 7, j = t & 127;
        float v = W1[t];
        if (c < CC) {
            if (j < CC) g_W1at[j * CC + c] = v;
            else        g_W1bt[(j - CC) * CC + c] = v;
        }
    } else {
        int t2 = t - 128 * 128;
        int o = t2 >> 7, c2 = t2 & 127;
        g_W2t[c2 * OO + o] = W2[t2];
    }
}

// ---------------------------------------------------------------------------
// Top-K insertion (sorted desc, static indices). Strict '>' keeps earliest
// index on ties, matching jax.lax.top_k.
// ---------------------------------------------------------------------------
__device__ __forceinline__ void topk_insert(float (&vals)[KK], int (&idxs)[KK],
                                            float v, int j) {
    vals[KK - 1] = v;
    idxs[KK - 1] = j;
#pragma unroll
    for (int p = KK - 1; p > 0; --p) {
        if (vals[p] > vals[p - 1]) {
            float tv = vals[p]; vals[p] = vals[p - 1]; vals[p - 1] = tv;
            int   ti = idxs[p]; idxs[p] = idxs[p - 1]; idxs[p - 1] = ti;
        }
    }
}

// ---------------------------------------------------------------------------
// KNN (monolithic, full candidate scan per query): 1 query per thread, xi
// packed as 32 f32x2 regs. Inner loop processes TWO candidates jointly
// (16 independent FMA chains) so LDS latency is hidden cross-candidate, and
// one combined guard halves the divergent-branch regions.
// rank = dot - 0.5*||xj||^2  (monotone in pd; xxi constant per query).
// ---------------------------------------------------------------------------
__global__ __launch_bounds__(128) void knn_kernel() {
    int b = blockIdx.y;
    int i = blockIdx.x * 128 + threadIdx.x;
    __shared__ __align__(16) float shx[128][CC];
    __shared__ float shxx[128];
    const float* xtb = g_xt + (size_t)b * NN * CC;

    u64 xi2[32];
    const float4* xir = (const float4*)(xtb + (size_t)i * CC);
#pragma unroll
    for (int q = 0; q < 16; q++) {
        float4 t = __ldg(&xir[q]);
        xi2[2 * q + 0] = pack2(t.x, t.y);
        xi2[2 * q + 1] = pack2(t.z, t.w);
    }

    float vals[KK]; int idxs[KK];
#pragma unroll
    for (int k = 0; k < KK; k++) { vals[k] = -3.0e38f; idxs[k] = 0; }

    for (int j0 = 0; j0 < NN; j0 += 128) {
        __syncthreads();
        const float4* src = (const float4*)(xtb + (size_t)j0 * CC);
        float4* dst = (float4*)shx;
#pragma unroll
        for (int r = 0; r < 16; r++) {
            int lin = r * 128 + threadIdx.x;
            dst[lin] = __ldg(&src[lin]);
        }
        shxx[threadIdx.x] = g_xx[b * NN + j0 + threadIdx.x];
        __syncthreads();

#pragma unroll 2
        for (int jl = 0; jl < 128; jl += 2) {
            const ulonglong2* r0 = (const ulonglong2*)shx[jl];      // broadcast
            const ulonglong2* r1 = (const ulonglong2*)shx[jl + 1];  // broadcast
            u64 a0 = 0ull, a1 = 0ull, a2 = 0ull, a3 = 0ull;
            u64 c0 = 0ull, c1 = 0ull, c2 = 0ull, c3 = 0ull;
#pragma unroll
            for (int q = 0; q < 8; q++) {
                ulonglong2 v0 = r0[2 * q];
                ulonglong2 v1 = r0[2 * q + 1];
                ulonglong2 w0 = r1[2 * q];
                ulonglong2 w1 = r1[2 * q + 1];
                a0 = fma2(xi2[4 * q + 0], v0.x, a0);
                c0 = fma2(xi2[4 * q + 0], w0.x, c0);
                a1 = fma2(xi2[4 * q + 1], v0.y, a1);
                c1 = fma2(xi2[4 * q + 1], w0.y, c1);
                a2 = fma2(xi2[4 * q + 2], v1.x, a2);
                c2 = fma2(xi2[4 * q + 2], w1.x, c2);
                a3 = fma2(xi2[4 * q + 3], v1.y, a3);
                c3 = fma2(xi2[4 * q + 3], w1.y, c3);
            }
            a0 = add2(a0, a1); a2 = add2(a2, a3); a0 = add2(a0, a2);
            c0 = add2(c0, c1); c2 = add2(c2, c3); c0 = add2(c0, c2);
            float lo0, hi0, lo1, hi1;
            unpack2(lo0, hi0, a0);
            unpack2(lo1, hi1, c0);
            float rank0 = lo0 + hi0 - shxx[jl];
            float rank1 = lo1 + hi1 - shxx[jl + 1];
            if (fmaxf(rank0, rank1) > vals[KK - 1]) {
                if (rank0 > vals[KK - 1]) topk_insert(vals, idxs, rank0, j0 + jl);
                if (rank1 > vals[KK - 1]) topk_insert(vals, idxs, rank1, j0 + jl + 1);
            }
        }
    }
    int* op = g_knn + ((size_t)b * NN + i) * KK;
#pragma unroll
    for (int k = 0; k < KK; k++) op[k] = idxs[k];
}

// ---------------------------------------------------------------------------
// Fused MLP (exact round-2 code, known 358us): 4 points/block; thread
// (p = tid>>6, c = tid&63) owns column c (<64) of point p.
// ---------------------------------------------------------------------------
__global__ __launch_bounds__(256) void mlp_kernel(float* __restrict__ out) {
    int b = blockIdx.y;
    int n0 = blockIdx.x * 4;
    int tid = threadIdx.x;
    int p = tid >> 6, c = tid & 63;

    __shared__ __align__(16) float nbrT[4][CC][24];  // diff[j][k], pitch 24
    __shared__ float xi_sh[4][CC];
    __shared__ int   idx_sh[4][KK];
    __shared__ float g_sh[4][2 * CC];

    const float* xtb = g_xt + (size_t)b * NN * CC;

    if (tid < 4 * KK) {
        int pp = tid / KK, k = tid % KK;
        idx_sh[pp][k] = g_knn[((size_t)b * NN + n0 + pp) * KK + k];
    }
    xi_sh[p][c] = __ldg(&xtb[(size_t)(n0 + p) * CC + c]);
    __syncthreads();

    // gather neighbors and form diff = xj - xi, stored transposed [c][k]
    for (int pp = 0; pp < 4; pp++) {
        for (int e = tid; e < KK * CC; e += 256) {
            int k = e >> 6, cc = e & 63;
            nbrT[pp][cc][k] =
                __ldg(&xtb[(size_t)idx_sh[pp][k] * CC + cc]) - xi_sh[pp][cc];
        }
    }
    __syncthreads();

    // h[k] for this thread's column c (<64) of point p
    float h[KK];
#pragma unroll
    for (int k = 0; k < KK; k++) h[k] = 0.f;
    float base = 0.f;
#pragma unroll 8
    for (int j = 0; j < CC; j++) {
        float w  = __ldg(&g_W1at[j * CC + c]);          // coalesced, L1-hot
        base    += __ldg(&g_W1bt[j * CC + c]) * xi_sh[p][j];
        const float4* f4 = (const float4*)nbrT[p][j];   // broadcast
#pragma unroll
        for (int q = 0; q < 5; q++) {
            float4 f = f4[q];
            h[4 * q + 0] += f.x * w;
            h[4 * q + 1] += f.y * w;
            h[4 * q + 2] += f.z * w;
            h[4 * q + 3] += f.w * w;
        }
    }

    // softmax over k, then g
    float m = -3.0e38f;
#pragma unroll
    for (int k = 0; k < KK; k++) { h[k] += base; m = fmaxf(m, h[k]); }
    float s = 0.f;
#pragma unroll
    for (int k = 0; k < KK; k++) { h[k] = __expf(h[k] - m); s += h[k]; }
    float inv = 1.f / s;
    float gdiff = 0.f;
#pragma unroll
    for (int k = 0; k < KK; k++) gdiff += nbrT[p][c][k] * h[k];
    g_sh[p][c]      = gdiff * inv;
    g_sh[p][CC + c] = xi_sh[p][c];  // softmax sums to 1 -> center passthrough
    __syncthreads();

    // out[o] = sum_c W2[o][c] * g[c]
    int o = tid & 127;
    int pb = (tid >> 7) * 2;
    for (int r = 0; r < 2; r++) {
        int pp = pb + r;
        float acc = 0.f;
#pragma unroll 16
        for (int cc = 0; cc < 2 * CC; cc++)
            acc += __ldg(&g_W2t[cc * OO + o]) * g_sh[pp][cc];
        out[(size_t)b * OO * NN + (size_t)o * NN + (n0 + pp)] = acc;
    }
}

// ---------------------------------------------------------------------------
extern "C" void kernel_launch(void* const* d_in, const int* in_sizes, int n_in,
                              void* d_out, int out_size) {
    const float* x  = (const float*)d_in[0];
    const float* W1 = (const float*)d_in[1];
    const float* W2 = (const float*)d_in[2];
    float* out = (float*)d_out;

    prep_x_kernel<<<dim3(NN / 32, BB), 256>>>(x);
    prep_w_kernel<<<128, 256>>>(W1, W2);
    knn_kernel<<<dim3(NN / 128, BB), 128>>>();
    mlp_kernel<<<dim3(NN / 4, BB), 256>>>(out);
}